// round 8
// baseline (speedup 1.0000x reference)
#include <cuda_runtime.h>
#include <cuda_bf16.h>
#include <cstdint>

#define NN 2048
#define BB 64
#define TT 512
#define CTAS 128
#define THREADS 512
#define PITCHB 4112                 // 2048*2 + 16 bytes, conflict-free ldmatrix rows

// ---- shared memory layout ----
#define OFF_WHI 0
#define OFF_WLO (16 * PITCHB)               // 65792
#define OFF_SPK (32 * PITCHB)               // 131584
#define SPK_STRIDE 68                       // u32 words per spike row (padded)
#define OFF_MEM (OFF_SPK + 64 * SPK_STRIDE * 4)   // 148992
#define OFF_RED (OFF_MEM + 64 * 16 * 4)           // 153088
#define OFF_LUT (OFF_RED + 8 * 64 * 16 * 4)       // 185856
#define SMEM_TOTAL (OFF_LUT + 128)                // 185984

// ---- persistent device state ----
__device__ __align__(16) __nv_bfloat16 g_Whi[NN * NN];    // [n][k] = 0.1*eff^T, hi
__device__ __align__(16) __nv_bfloat16 g_Wlo[NN * NN];    // residual
// tagged spike exchange: word = (tag<<16) | 16 spike bits, [parity][row*128 + cta]
__device__ __align__(16) uint32_t g_spkT[2][BB * CTAS];

// Spike bit permutation: within each 16-bit group, local c = k&15 sits at
//   np(c) = ((c&7)>>1)*4 + (c&1) + 2*((c>>3)&1)
// so nibble q = bits {k=2q, 2q+1, 2q+8, 2q+9}: one lane's A-pair bits.

// ---- helpers ----
__device__ __forceinline__ uint32_t smem_u32(const void* p) {
    uint32_t a;
    asm("{ .reg .u64 t; cvta.to.shared.u64 t, %1; cvt.u32.u64 %0, t; }" : "=r"(a) : "l"(p));
    return a;
}

__device__ __forceinline__ void ldsm4(uint32_t* r, uint32_t addr) {
    asm volatile("ldmatrix.sync.aligned.m8n8.x4.shared.b16 {%0,%1,%2,%3}, [%4];"
                 : "=r"(r[0]), "=r"(r[1]), "=r"(r[2]), "=r"(r[3]) : "r"(addr));
}

__device__ __forceinline__ void mma_bf16(float* c, const uint32_t* a, uint32_t b0, uint32_t b1) {
    asm volatile(
        "mma.sync.aligned.m16n8k16.row.col.f32.bf16.bf16.f32 "
        "{%0,%1,%2,%3},{%4,%5,%6,%7},{%8,%9},{%0,%1,%2,%3};"
        : "+f"(c[0]), "+f"(c[1]), "+f"(c[2]), "+f"(c[3])
        : "r"(a[0]), "r"(a[1]), "r"(a[2]), "r"(a[3]), "r"(b0), "r"(b1));
}

__device__ __forceinline__ uint4 ldcg4(const uint32_t* p) {
    uint4 v;
    asm volatile("ld.global.cg.v4.u32 {%0,%1,%2,%3}, [%4];"
                 : "=r"(v.x), "=r"(v.y), "=r"(v.z), "=r"(v.w) : "l"(p));
    return v;
}

__device__ __forceinline__ void stcg(uint32_t* p, uint32_t v) {
    asm volatile("st.global.cg.u32 [%0], %1;" :: "l"(p), "r"(v) : "memory");
}

__device__ __forceinline__ bool tag_ok(uint4 v, uint32_t want) {
    return ((v.x >> 16) == want) & ((v.y >> 16) == want) &
           ((v.z >> 16) == want) & ((v.w >> 16) == want);
}

// ---- prep: transpose + zero diag + 0.1 scale + bf16 hi/lo split, plus state init ----
__global__ void prep_kernel(const float* __restrict__ rec) {
    __shared__ float tile[32][33];
    int k = blockIdx.y * 32 + threadIdx.y;
    int n = blockIdx.x * 32 + threadIdx.x;
    tile[threadIdx.y][threadIdx.x] = rec[k * NN + n];

    // state init folded in: 16384 tagged words -> first 16 blocks (1024 thr each)
    int fb = blockIdx.y * gridDim.x + blockIdx.x;
    int ft = threadIdx.y * 32 + threadIdx.x;
    if (fb < 8)       g_spkT[0][fb * 1024 + ft] = 0u;   // tag 0, spikes 0
    else if (fb < 16) g_spkT[1][(fb - 8) * 1024 + ft] = 0u;

    __syncthreads();
    int nn = blockIdx.x * 32 + threadIdx.y;
    int kk = blockIdx.y * 32 + threadIdx.x;
    float w = tile[threadIdx.x][threadIdx.y];      // rec[kk][nn]
    float v = (nn == kk) ? 0.0f : 0.1f * w;
    __nv_bfloat16 hi = __float2bfloat16(v);
    float resid = v - __bfloat162float(hi);
    g_Whi[nn * NN + kk] = hi;
    g_Wlo[nn * NN + kk] = __float2bfloat16(resid);
}

// ---- persistent RSNN kernel: 128 CTAs, one per 16-neuron slice ----
__global__ void __launch_bounds__(THREADS, 1)
rsnn_kernel(const float* __restrict__ x, float* __restrict__ out) {
    extern __shared__ char smem[];
    const uint32_t sbase = smem_u32(smem);

    const int tid = threadIdx.x;
    const int wid = tid >> 5;
    const int lane = tid & 31;
    const int n0 = blockIdx.x * 16;

    // ---- load weight slice into SMEM once (hi + lo, pitched) ----
    for (int i = tid; i < 16 * 256; i += THREADS) {
        int row = i >> 8, c = i & 255;
        *(uint4*)(smem + OFF_WHI + row * PITCHB + c * 16) =
            *(const uint4*)(g_Whi + (size_t)(n0 + row) * NN + c * 8);
        *(uint4*)(smem + OFF_WLO + row * PITCHB + c * 16) =
            *(const uint4*)(g_Wlo + (size_t)(n0 + row) * NN + c * 8);
    }
    for (int i = tid; i < 64 * 16; i += THREADS)
        ((float*)(smem + OFF_MEM))[i] = 0.0f;
    // nibble -> (a_low, a_high) bf16x2 LUT
    if (tid < 16) {
        uint2 e;
        e.x = ((tid & 1) ? 0x00003F80u : 0u) | ((tid & 2) ? 0x3F800000u : 0u);
        e.y = ((tid & 4) ? 0x00003F80u : 0u) | ((tid & 8) ? 0x3F800000u : 0u);
        ((uint2*)(smem + OFF_LUT))[tid] = e;
    }
    __syncthreads();

    // per-thread constants (GEMM, warps 0-7: k-eighths)
    const int rowq = lane >> 2;           // 0..7
    const int q4 = (lane & 3) * 4;        // nibble shift within a 16-bit half
    const int c0 = (lane & 3) * 2;
    uint32_t ldsm_off;
    {
        int grp = lane >> 3;                          // 8x8 matrix select
        int row = ((grp >> 1) << 3) + (lane & 7);     // local neuron row 0..15
        int koff = (grp & 1) * 8;
        ldsm_off = row * PITCHB + koff * 2;
    }
    // per-thread constants (epilogue: all 512 threads, 2 cols each)
    const int eb = tid >> 3;              // batch row 0..63
    const int cp = tid & 7;               // col pair 0..7
    const int ec = cp * 2;
    const int wsel = n0 >> 5;
    const int hsh = ((n0 >> 4) & 1) * 16;

    int npos[2];
    uint32_t pmask[2];
    #pragma unroll
    for (int i = 0; i < 2; ++i) {
        int c = ec + i;
        npos[i] = ((c & 7) >> 1) * 4 + (c & 1) + 2 * ((c >> 3) & 1);
        pmask[i] = 1u << (hsh + npos[i]);
    }
    // swizzled reduce address (conflict-free): phys pair = (cp + ((eb&2)<<1)) & 7
    const int red_off = eb * 16 + ((cp + ((eb & 2) << 1)) & 7) * 2;

    // staging chunks: thread handles chunks tid and tid+512 (8 tagged words each)
    const int k0 = tid, k1 = tid + 512;
    const int row0 = k0 >> 4, cta0 = (k0 & 15) * 8;
    const int row1 = k1 >> 4, cta1 = (k1 & 15) * 8;

    uint32_t* const spkS = (uint32_t*)(smem + OFF_SPK);
    float* const memS = (float*)(smem + OFF_MEM);
    float* const redS = (float*)(smem + OFF_RED);
    const uint2* const lutS = (const uint2*)(smem + OFF_LUT);

    for (int t = 0; t < TT; ++t) {
        const uint32_t* gsrc = g_spkT[t & 1];
        uint32_t* gdst = g_spkT[(t + 1) & 1];
        const uint32_t want = (uint32_t)t;

        // ---- prefetch x for this step ----
        float2 xv = __ldg((const float2*)(x + ((size_t)eb * TT + t) * NN + n0 + ec));

        // ---- stage: poll tagged spike words, strip tags, pack pairs into spkS ----
        {
            const uint32_t* p0 = gsrc + row0 * 128 + cta0;
            const uint32_t* p1 = gsrc + row1 * 128 + cta1;
            uint4 a0 = ldcg4(p0), a1 = ldcg4(p0 + 4);
            uint4 b0 = ldcg4(p1), b1 = ldcg4(p1 + 4);
            while (!(tag_ok(a0, want) & tag_ok(a1, want) &
                     tag_ok(b0, want) & tag_ok(b1, want))) {
                __nanosleep(128);
                a0 = ldcg4(p0); a1 = ldcg4(p0 + 4);
                b0 = ldcg4(p1); b1 = ldcg4(p1 + 4);
            }
            uint4 pa, pb;
            pa.x = (a0.x & 0xFFFFu) | (a0.y << 16);
            pa.y = (a0.z & 0xFFFFu) | (a0.w << 16);
            pa.z = (a1.x & 0xFFFFu) | (a1.y << 16);
            pa.w = (a1.z & 0xFFFFu) | (a1.w << 16);
            pb.x = (b0.x & 0xFFFFu) | (b0.y << 16);
            pb.y = (b0.z & 0xFFFFu) | (b0.w << 16);
            pb.z = (b1.x & 0xFFFFu) | (b1.y << 16);
            pb.w = (b1.z & 0xFFFFu) | (b1.w << 16);
            *(uint4*)(smem + OFF_SPK + (row0 * SPK_STRIDE + cta0 / 2) * 4) = pa;
            *(uint4*)(smem + OFF_SPK + (row1 * SPK_STRIDE + cta1 / 2) * 4) = pb;
        }
        __syncthreads();

        // hoist prev-spike word (reset mask) so epilogue never touches spkS
        const uint32_t pw = spkS[eb * SPK_STRIDE + wsel];

        // ---- GEMM: warps 0-7, warp owns a k-eighth, all 4 m-tiles, 16 cols ----
        if (wid < 8) {
            float acc[4][2][4];
            #pragma unroll
            for (int m = 0; m < 4; ++m)
                #pragma unroll
                for (int nh = 0; nh < 2; ++nh)
                    #pragma unroll
                    for (int e = 0; e < 4; ++e) acc[m][nh][e] = 0.0f;

            #pragma unroll 2
            for (int j = 0; j < 8; ++j) {
                const int widx = (wid << 3) + j;          // u32 spike word index
                uint32_t bh[2][4], bl[2][4];
                #pragma unroll
                for (int h = 0; h < 2; ++h) {
                    const int kt = widx * 2 + h;
                    ldsm4(bh[h], sbase + OFF_WHI + ldsm_off + kt * 32);
                    ldsm4(bl[h], sbase + OFF_WLO + ldsm_off + kt * 32);
                }
                #pragma unroll
                for (int m = 0; m < 4; ++m) {
                    const uint32_t w0 = spkS[(m * 16 + rowq) * SPK_STRIDE + widx];
                    const uint32_t w1 = spkS[(m * 16 + rowq + 8) * SPK_STRIDE + widx];
                    #pragma unroll
                    for (int h = 0; h < 2; ++h) {
                        uint2 u0 = lutS[(w0 >> (h * 16 + q4)) & 0xFu];
                        uint2 u1 = lutS[(w1 >> (h * 16 + q4)) & 0xFu];
                        uint32_t a[4] = {u0.x, u1.x, u0.y, u1.y};
                        mma_bf16(acc[m][0], a, bh[h][0], bh[h][1]);
                        mma_bf16(acc[m][1], a, bh[h][2], bh[h][3]);
                        mma_bf16(acc[m][0], a, bl[h][0], bl[h][1]);
                        mma_bf16(acc[m][1], a, bl[h][2], bl[h][3]);
                    }
                }
            }

            // ---- dump (swizzled, conflict-free STS.64) ----
            float* pwrt = redS + wid * 1024;
            #pragma unroll
            for (int m = 0; m < 4; ++m)
                #pragma unroll
                for (int nh = 0; nh < 2; ++nh) {
                    const int mycp = nh * 4 + (lane & 3);
                    const int r0 = m * 16 + rowq;
                    const int sw = ((mycp + ((r0 & 2) << 1)) & 7) * 2;
                    *(float2*)(pwrt + r0 * 16 + sw) = make_float2(acc[m][nh][0], acc[m][nh][1]);
                    *(float2*)(pwrt + (r0 + 8) * 16 + sw) = make_float2(acc[m][nh][2], acc[m][nh][3]);
                }
        }
        __syncthreads();

        // ---- reduce 8 partials + LIF epilogue (all 512 threads, 2 cols each) ----
        float2 s = *(float2*)(redS + red_off);
        #pragma unroll
        for (int w = 1; w < 8; ++w) {
            float2 p = *(float2*)(redS + w * 1024 + red_off);
            s.x += p.x; s.y += p.y;
        }

        float2 mv = *(float2*)(memS + eb * 16 + ec);
        float cur0 = xv.x + s.x, cur1 = xv.y + s.y;
        float m0 = (pw & pmask[0]) ? cur0 : fmaf(0.96f, mv.x, cur0);
        float m1 = (pw & pmask[1]) ? cur1 : fmaf(0.96f, mv.y, cur1);
        unsigned s0 = (m0 >= 0.5f), s1 = (m1 >= 0.5f);

        // publish spikes FIRST (tagged word per batch row)
        unsigned v = (s0 << npos[0]) | (s1 << npos[1]);
        v |= __shfl_xor_sync(0xFFFFFFFFu, v, 1);
        v |= __shfl_xor_sync(0xFFFFFFFFu, v, 2);
        v |= __shfl_xor_sync(0xFFFFFFFFu, v, 4);
        if ((tid & 7) == 0)
            stcg(gdst + eb * 128 + blockIdx.x, ((uint32_t)(t + 1) << 16) | (v & 0xFFFFu));

        // state + output stores (off the publish critical path)
        *(float2*)(memS + eb * 16 + ec) = make_float2(m0, m1);
        *(float2*)(out + ((size_t)eb * TT + t) * NN + n0 + ec) =
            make_float2((float)s0, (float)s1);
        // no sync needed here: next stage's __syncthreads orders spkS/redS reuse
    }
}

// ---- launch ----
extern "C" void kernel_launch(void* const* d_in, const int* in_sizes, int n_in,
                              void* d_out, int out_size) {
    const float* x = (const float*)d_in[0];
    const float* rec = (const float*)d_in[1];
    if (n_in >= 2 && in_sizes[0] == NN * NN) {
        x = (const float*)d_in[1];
        rec = (const float*)d_in[0];
    }
    float* out = (float*)d_out;

    cudaFuncSetAttribute(rsnn_kernel, cudaFuncAttributeMaxDynamicSharedMemorySize, SMEM_TOTAL);

    dim3 cg(NN / 32, NN / 32), cb(32, 32);
    prep_kernel<<<cg, cb>>>(rec);
    rsnn_kernel<<<CTAS, THREADS, SMEM_TOTAL>>>(x, out);
}

// round 9
// speedup vs baseline: 1.9251x; 1.9251x over previous
#include <cuda_runtime.h>
#include <cuda_bf16.h>
#include <cstdint>

#define NN 2048
#define BB 64
#define TT 512
#define CTAS 128
#define THREADS 256
#define PITCHB 4112                 // 2048*2 + 16 bytes, conflict-free ldmatrix rows

// ---- shared memory layout ----
#define OFF_WHI 0
#define OFF_WLO (16 * PITCHB)               // 65792
#define OFF_SPK (32 * PITCHB)               // 131584
#define SPK_STRIDE 68                       // u32 words per spike row (padded)
#define OFF_MEM (OFF_SPK + 64 * SPK_STRIDE * 4)   // 148992
#define OFF_RED (OFF_MEM + 64 * 16 * 4)           // 153088
#define OFF_LUT (OFF_RED + 8 * 64 * 16 * 4)       // 185856
#define SMEM_TOTAL (OFF_LUT + 128)                // 185984

// ---- persistent device state ----
__device__ __align__(16) __nv_bfloat16 g_Whi[NN * NN];    // [n][k] = 0.1*eff^T, hi
__device__ __align__(16) __nv_bfloat16 g_Wlo[NN * NN];    // residual
__device__ __align__(16) uint32_t g_spk0[BB * (NN / 32)]; // bit-permuted packed spikes
__device__ __align__(16) uint32_t g_spk1[BB * (NN / 32)];
__device__ uint32_t g_bar;

// Spike bit permutation: within each 16-bit half (h = k>=16), local c = k&15 sits at
//   np(c) = ((c&7)>>1)*4 + (c&1) + 2*((c>>3)&1)
// so nibble q of a half = bits {k=2q, 2q+1, 2q+8, 2q+9}: one lane's A-pair bits.

// ---- helpers ----
__device__ __forceinline__ uint32_t smem_u32(const void* p) {
    uint32_t a;
    asm("{ .reg .u64 t; cvta.to.shared.u64 t, %1; cvt.u32.u64 %0, t; }" : "=r"(a) : "l"(p));
    return a;
}

__device__ __forceinline__ void ldsm4(uint32_t* r, uint32_t addr) {
    asm volatile("ldmatrix.sync.aligned.m8n8.x4.shared.b16 {%0,%1,%2,%3}, [%4];"
                 : "=r"(r[0]), "=r"(r[1]), "=r"(r[2]), "=r"(r[3]) : "r"(addr));
}

__device__ __forceinline__ void mma_bf16(float* c, const uint32_t* a, uint32_t b0, uint32_t b1) {
    asm volatile(
        "mma.sync.aligned.m16n8k16.row.col.f32.bf16.bf16.f32 "
        "{%0,%1,%2,%3},{%4,%5,%6,%7},{%8,%9},{%0,%1,%2,%3};"
        : "+f"(c[0]), "+f"(c[1]), "+f"(c[2]), "+f"(c[3])
        : "r"(a[0]), "r"(a[1]), "r"(a[2]), "r"(a[3]), "r"(b0), "r"(b1));
}

// ---- prep: transpose + zero diag + 0.1 scale + bf16 hi/lo split, plus state init ----
__global__ void prep_kernel(const float* __restrict__ rec) {
    __shared__ float tile[32][33];
    int k = blockIdx.y * 32 + threadIdx.y;
    int n = blockIdx.x * 32 + threadIdx.x;
    tile[threadIdx.y][threadIdx.x] = rec[k * NN + n];

    int fb = blockIdx.y * gridDim.x + blockIdx.x;
    int ft = threadIdx.y * 32 + threadIdx.x;
    if (fb < 4)      g_spk0[fb * 1024 + ft] = 0u;
    else if (fb < 8) g_spk1[(fb - 4) * 1024 + ft] = 0u;
    else if (fb == 8 && ft == 0) g_bar = 0u;

    __syncthreads();
    int nn = blockIdx.x * 32 + threadIdx.y;
    int kk = blockIdx.y * 32 + threadIdx.x;
    float w = tile[threadIdx.x][threadIdx.y];      // rec[kk][nn]
    float v = (nn == kk) ? 0.0f : 0.1f * w;
    __nv_bfloat16 hi = __float2bfloat16(v);
    float resid = v - __bfloat162float(hi);
    g_Whi[nn * NN + kk] = hi;
    g_Wlo[nn * NN + kk] = __float2bfloat16(resid);
}

// ---- persistent RSNN kernel: 128 CTAs, one per 16-neuron slice, 8 warps ----
__global__ void __launch_bounds__(THREADS)
rsnn_kernel(const float* __restrict__ x, float* __restrict__ out) {
    extern __shared__ char smem[];
    const uint32_t sbase = smem_u32(smem);

    const int tid = threadIdx.x;
    const int wid = tid >> 5;           // warp = k-eighth (8 u32 spike words)
    const int lane = tid & 31;
    const int n0 = blockIdx.x * 16;

    // ---- load weight slice into SMEM once (hi + lo, pitched) ----
    for (int i = tid; i < 16 * 256; i += THREADS) {
        int row = i >> 8, c = i & 255;
        *(uint4*)(smem + OFF_WHI + row * PITCHB + c * 16) =
            *(const uint4*)(g_Whi + (size_t)(n0 + row) * NN + c * 8);
        *(uint4*)(smem + OFF_WLO + row * PITCHB + c * 16) =
            *(const uint4*)(g_Wlo + (size_t)(n0 + row) * NN + c * 8);
    }
    for (int i = tid; i < 64 * 16; i += THREADS)
        ((float*)(smem + OFF_MEM))[i] = 0.0f;
    // nibble -> (a_low, a_high) bf16x2 LUT; conflict-free bank sweep
    if (tid < 16) {
        uint2 e;
        e.x = ((tid & 1) ? 0x00003F80u : 0u) | ((tid & 2) ? 0x3F800000u : 0u);
        e.y = ((tid & 4) ? 0x00003F80u : 0u) | ((tid & 8) ? 0x3F800000u : 0u);
        ((uint2*)(smem + OFF_LUT))[tid] = e;
    }
    __syncthreads();

    // per-thread constants (GEMM)
    const int rowq = lane >> 2;           // 0..7
    const int q4 = (lane & 3) * 4;        // nibble shift within a 16-bit half
    const int lc = lane & 3;
    uint32_t ldsm_off;
    {
        int grp = lane >> 3;                          // 8x8 matrix select
        int row = ((grp >> 1) << 3) + (lane & 7);     // local neuron row 0..15
        int koff = (grp & 1) * 8;
        ldsm_off = row * PITCHB + koff * 2;
    }

    // ---- hoist ALL B fragments (hi + lo) into registers: loaded ONCE ----
    uint32_t bhr[8][2][4], blr[8][2][4];
    #pragma unroll
    for (int j = 0; j < 8; ++j) {
        const int widx = (wid << 3) + j;
        #pragma unroll
        for (int h = 0; h < 2; ++h) {
            const int kt = widx * 2 + h;
            ldsm4(bhr[j][h], sbase + OFF_WHI + ldsm_off + kt * 32);
            ldsm4(blr[j][h], sbase + OFF_WLO + ldsm_off + kt * 32);
        }
    }

    // per-thread constants (epilogue: 256 threads, 4 cols each)
    const int eb = tid >> 2;              // batch row 0..63
    const int eq = (tid & 3) * 4;         // col base 0..12
    const int wsel = n0 >> 5;
    const int hsh = ((n0 >> 4) & 1) * 16;

    int npos[4];
    uint32_t pmask[4];
    #pragma unroll
    for (int i = 0; i < 4; ++i) {
        int c = eq + i;
        npos[i] = ((c & 7) >> 1) * 4 + (c & 1) + 2 * ((c >> 3) & 1);
        pmask[i] = 1u << (hsh + npos[i]);
    }
    // swizzled reduce pair offsets (pair swizzle: p = (cp + ((eb&2)<<1)) & 7)
    const int cp0 = (tid & 3) * 2;
    const int rp0 = eb * 16 + ((cp0 + ((eb & 2) << 1)) & 7) * 2;
    const int rp1 = eb * 16 + (((cp0 + 1) + ((eb & 2) << 1)) & 7) * 2;

    uint32_t* const spkS = (uint32_t*)(smem + OFF_SPK);
    float* const memS = (float*)(smem + OFF_MEM);
    float* const redS = (float*)(smem + OFF_RED);
    const uint2* const lutS = (const uint2*)(smem + OFF_LUT);

    for (int t = 0; t < TT; ++t) {
        const uint32_t* gsrc = (t & 1) ? g_spk1 : g_spk0;
        uint32_t* gdst = (t & 1) ? g_spk0 : g_spk1;

        // ---- prefetch x for this step ----
        float4 xv = __ldg((const float4*)(x + ((size_t)eb * TT + t) * NN + n0 + eq));

        // ---- stage packed spikes [64 x 64 u32] -> padded SMEM rows ----
        {
            const uint4* src = (const uint4*)gsrc;
            #pragma unroll
            for (int i = tid; i < 1024; i += THREADS) {
                int row = i >> 4, c4 = i & 15;
                uint4 v = __ldcg(src + i);
                *(uint4*)(smem + OFF_SPK + (row * SPK_STRIDE + c4 * 4) * 4) = v;
            }
        }
        __syncthreads();

        // ---- GEMM: warp owns a k-eighth, B resident in registers ----
        float acc[4][2][4];
        #pragma unroll
        for (int m = 0; m < 4; ++m)
            #pragma unroll
            for (int nh = 0; nh < 2; ++nh)
                #pragma unroll
                for (int e = 0; e < 4; ++e) acc[m][nh][e] = 0.0f;

        #pragma unroll
        for (int j = 0; j < 8; ++j) {
            const int widx = (wid << 3) + j;          // u32 spike word index
            #pragma unroll
            for (int m = 0; m < 4; ++m) {
                const uint32_t w0 = spkS[(m * 16 + rowq) * SPK_STRIDE + widx];
                const uint32_t w1 = spkS[(m * 16 + rowq + 8) * SPK_STRIDE + widx];
                #pragma unroll
                for (int h = 0; h < 2; ++h) {
                    uint2 u0 = lutS[(w0 >> (h * 16 + q4)) & 0xFu];
                    uint2 u1 = lutS[(w1 >> (h * 16 + q4)) & 0xFu];
                    uint32_t a[4] = {u0.x, u1.x, u0.y, u1.y};
                    mma_bf16(acc[m][0], a, bhr[j][h][0], bhr[j][h][1]);
                    mma_bf16(acc[m][1], a, bhr[j][h][2], bhr[j][h][3]);
                    mma_bf16(acc[m][0], a, blr[j][h][0], blr[j][h][1]);
                    mma_bf16(acc[m][1], a, blr[j][h][2], blr[j][h][3]);
                }
            }
        }

        // ---- dump per-warp partials (pair-swizzled: 2-way instead of 4-way) ----
        {
            float* pwrt = redS + wid * 1024;
            #pragma unroll
            for (int m = 0; m < 4; ++m)
                #pragma unroll
                for (int nh = 0; nh < 2; ++nh) {
                    const int mycp = nh * 4 + lc;
                    const int r0 = m * 16 + rowq;
                    const int sw = ((mycp + ((r0 & 2) << 1)) & 7) * 2;
                    *(float2*)(pwrt + r0 * 16 + sw) = make_float2(acc[m][nh][0], acc[m][nh][1]);
                    *(float2*)(pwrt + (r0 + 8) * 16 + sw) = make_float2(acc[m][nh][2], acc[m][nh][3]);
                }
        }
        __syncthreads();

        // ---- reduce 8 partials + LIF epilogue (4 cols per thread) ----
        float2 sa = *(float2*)(redS + rp0);
        float2 sb = *(float2*)(redS + rp1);
        #pragma unroll
        for (int w = 1; w < 8; ++w) {
            float2 pa = *(float2*)(redS + w * 1024 + rp0);
            float2 pb = *(float2*)(redS + w * 1024 + rp1);
            sa.x += pa.x; sa.y += pa.y;
            sb.x += pb.x; sb.y += pb.y;
        }

        float4 mv = *(float4*)(memS + eb * 16 + eq);
        const uint32_t pw = spkS[eb * SPK_STRIDE + wsel];

        float cur0 = xv.x + sa.x, cur1 = xv.y + sa.y;
        float cur2 = xv.z + sb.x, cur3 = xv.w + sb.y;
        float m0 = (pw & pmask[0]) ? cur0 : fmaf(0.96f, mv.x, cur0);
        float m1 = (pw & pmask[1]) ? cur1 : fmaf(0.96f, mv.y, cur1);
        float m2 = (pw & pmask[2]) ? cur2 : fmaf(0.96f, mv.z, cur2);
        float m3 = (pw & pmask[3]) ? cur3 : fmaf(0.96f, mv.w, cur3);

        unsigned s0 = (m0 >= 0.5f), s1 = (m1 >= 0.5f);
        unsigned s2 = (m2 >= 0.5f), s3 = (m3 >= 0.5f);

        *(float4*)(memS + eb * 16 + eq) = make_float4(m0, m1, m2, m3);

        // pack new spike bits (permuted positions) -> u16 per (batch row, CTA)
        unsigned v = (s0 << npos[0]) | (s1 << npos[1]) | (s2 << npos[2]) | (s3 << npos[3]);
        v |= __shfl_xor_sync(0xFFFFFFFFu, v, 1);
        v |= __shfl_xor_sync(0xFFFFFFFFu, v, 2);
        if ((tid & 3) == 0)
            ((uint16_t*)gdst)[eb * 128 + blockIdx.x] = (uint16_t)v;

        // ---- barrier arrive (spikes visible), overlap out-store with wait ----
        __syncthreads();
        if (tid == 0)
            asm volatile("red.release.gpu.global.add.u32 [%0], 1;" :: "l"(&g_bar) : "memory");

        *(float4*)(out + ((size_t)eb * TT + t) * NN + n0 + eq) =
            make_float4((float)s0, (float)s1, (float)s2, (float)s3);

        if (tid == 0) {
            const unsigned tgt = (unsigned)(CTAS * (t + 1));
            unsigned bv;
            do {
                asm volatile("ld.acquire.gpu.global.u32 %0, [%1];" : "=r"(bv) : "l"(&g_bar) : "memory");
            } while (bv < tgt);
        }
        __syncthreads();
    }
}

// ---- launch ----
extern "C" void kernel_launch(void* const* d_in, const int* in_sizes, int n_in,
                              void* d_out, int out_size) {
    const float* x = (const float*)d_in[0];
    const float* rec = (const float*)d_in[1];
    if (n_in >= 2 && in_sizes[0] == NN * NN) {
        x = (const float*)d_in[1];
        rec = (const float*)d_in[0];
    }
    float* out = (float*)d_out;

    cudaFuncSetAttribute(rsnn_kernel, cudaFuncAttributeMaxDynamicSharedMemorySize, SMEM_TOTAL);

    dim3 cg(NN / 32, NN / 32), cb(32, 32);
    prep_kernel<<<cg, cb>>>(rec);
    rsnn_kernel<<<CTAS, THREADS, SMEM_TOTAL>>>(x, out);
}